// round 1
// baseline (speedup 1.0000x reference)
#include <cuda_runtime.h>

// FCGAT reduces algebraically to: out = relu(X @ W^T + b)
//   X = x reshaped [M=32768, K=256]   (d_in[0])
//   W = W_w [256, 256] row-major, out[m,e] = sum_d X[m,d]*W[e,d]  (d_in[1])
//   b = W_b [256]                      (d_in[2])
// because softmax over axis=2 followed by einsum('nkj,nkd->nkd') multiplies h by
// sum_j softmax(...)[j] == 1. att_w / att_b are dead inputs.

#define MDIM 32768
#define NDIM 256
#define KDIM 256
#define TM 128
#define TN 128
#define TK 16
#define PAD 4

__global__ __launch_bounds__(256, 2)
void fcgat_gemm_bias_relu(const float* __restrict__ X,
                          const float* __restrict__ W,
                          const float* __restrict__ bias,
                          float* __restrict__ out)
{
    __shared__ float As[2][TK][TM + PAD];   // As[k][m]
    __shared__ float Bs[2][TK][TN + PAD];   // Bs[k][n]  (n = output col e)

    const int bm  = blockIdx.y * TM;
    const int bn  = blockIdx.x * TN;
    const int tid = threadIdx.x;
    const int tx  = tid & 15;       // 16 col groups
    const int ty  = tid >> 4;       // 16 row groups
    const int row0 = ty * 8;
    const int col0 = tx * 8;

    // Global-load mapping: per K-tile, A needs 128x16 floats = 512 float4,
    // B needs 128x16 = 512 float4; 2 of each per thread (256 threads).
    float4 aTmp[2], bTmp[2];

    float acc[8][8] = {};

    // ---- prologue: load tile 0 ----
#pragma unroll
    for (int i = 0; i < 2; i++) {
        int p  = tid + i * 256;
        int r  = p >> 2;          // row within tile (A: m, B: e)
        int kv = p & 3;           // which float4 along k
        aTmp[i] = *reinterpret_cast<const float4*>(
            &X[(size_t)(bm + r) * KDIM + kv * 4]);
        bTmp[i] = *reinterpret_cast<const float4*>(
            &W[(size_t)(bn + r) * KDIM + kv * 4]);
    }
#pragma unroll
    for (int i = 0; i < 2; i++) {
        int p  = tid + i * 256;
        int r  = p >> 2;
        int kv = p & 3;
        As[0][kv * 4 + 0][r] = aTmp[i].x;
        As[0][kv * 4 + 1][r] = aTmp[i].y;
        As[0][kv * 4 + 2][r] = aTmp[i].z;
        As[0][kv * 4 + 3][r] = aTmp[i].w;
        Bs[0][kv * 4 + 0][r] = bTmp[i].x;
        Bs[0][kv * 4 + 1][r] = bTmp[i].y;
        Bs[0][kv * 4 + 2][r] = bTmp[i].z;
        Bs[0][kv * 4 + 3][r] = bTmp[i].w;
    }
    __syncthreads();

    const int NKT = KDIM / TK;   // 16 K-tiles
    int buf = 0;
#pragma unroll 1
    for (int kt = 0; kt < NKT; kt++) {
        // prefetch next tile into registers (overlaps with compute)
        if (kt + 1 < NKT) {
#pragma unroll
            for (int i = 0; i < 2; i++) {
                int p  = tid + i * 256;
                int r  = p >> 2;
                int kv = p & 3;
                int kg = (kt + 1) * TK + kv * 4;
                aTmp[i] = *reinterpret_cast<const float4*>(
                    &X[(size_t)(bm + r) * KDIM + kg]);
                bTmp[i] = *reinterpret_cast<const float4*>(
                    &W[(size_t)(bn + r) * KDIM + kg]);
            }
        }

        // ---- compute on current buffer ----
#pragma unroll
        for (int k = 0; k < TK; k++) {
            float a[8], b[8];
#pragma unroll
            for (int i = 0; i < 8; i += 4) {
                float4 v = *reinterpret_cast<const float4*>(&As[buf][k][row0 + i]);
                a[i + 0] = v.x; a[i + 1] = v.y; a[i + 2] = v.z; a[i + 3] = v.w;
            }
#pragma unroll
            for (int j = 0; j < 8; j += 4) {
                float4 v = *reinterpret_cast<const float4*>(&Bs[buf][k][col0 + j]);
                b[j + 0] = v.x; b[j + 1] = v.y; b[j + 2] = v.z; b[j + 3] = v.w;
            }
#pragma unroll
            for (int i = 0; i < 8; i++)
#pragma unroll
                for (int j = 0; j < 8; j++)
                    acc[i][j] = fmaf(a[i], b[j], acc[i][j]);
        }

        // ---- stage next tile into the other buffer ----
        if (kt + 1 < NKT) {
#pragma unroll
            for (int i = 0; i < 2; i++) {
                int p  = tid + i * 256;
                int r  = p >> 2;
                int kv = p & 3;
                As[buf ^ 1][kv * 4 + 0][r] = aTmp[i].x;
                As[buf ^ 1][kv * 4 + 1][r] = aTmp[i].y;
                As[buf ^ 1][kv * 4 + 2][r] = aTmp[i].z;
                As[buf ^ 1][kv * 4 + 3][r] = aTmp[i].w;
                Bs[buf ^ 1][kv * 4 + 0][r] = bTmp[i].x;
                Bs[buf ^ 1][kv * 4 + 1][r] = bTmp[i].y;
                Bs[buf ^ 1][kv * 4 + 2][r] = bTmp[i].z;
                Bs[buf ^ 1][kv * 4 + 3][r] = bTmp[i].w;
            }
            __syncthreads();
            buf ^= 1;
        }
    }

    // ---- epilogue: bias + relu, float4 stores ----
#pragma unroll
    for (int i = 0; i < 8; i++) {
        size_t m = (size_t)(bm + row0 + i);
#pragma unroll
        for (int j = 0; j < 8; j += 4) {
            int n = bn + col0 + j;
            float4 v;
            v.x = acc[i][j + 0] + bias[n + 0];
            v.y = acc[i][j + 1] + bias[n + 1];
            v.z = acc[i][j + 2] + bias[n + 2];
            v.w = acc[i][j + 3] + bias[n + 3];
            v.x = v.x > 0.f ? v.x : 0.f;
            v.y = v.y > 0.f ? v.y : 0.f;
            v.z = v.z > 0.f ? v.z : 0.f;
            v.w = v.w > 0.f ? v.w : 0.f;
            *reinterpret_cast<float4*>(&out[m * NDIM + n]) = v;
        }
    }
}

extern "C" void kernel_launch(void* const* d_in, const int* in_sizes, int n_in,
                              void* d_out, int out_size)
{
    const float* x  = (const float*)d_in[0];   // [64,512,256] -> [32768,256]
    const float* Ww = (const float*)d_in[1];   // [256,256]
    const float* Wb = (const float*)d_in[2];   // [256]
    // d_in[3] (att_w) and d_in[4] (att_b) are mathematically dead: softmax rows sum to 1.

    float* out = (float*)d_out;                // [32768,256] fp32

    dim3 grid(NDIM / TN, MDIM / TM);           // (2, 256) = 512 CTAs
    fcgat_gemm_bias_relu<<<grid, 256>>>(x, Ww, Wb, out);
}

// round 6
// speedup vs baseline: 2.3587x; 2.3587x over previous
#include <cuda_runtime.h>
#include <cuda_bf16.h>
#include <cstdint>

// FCGAT collapses to: out = relu(X @ W^T + b)  (proven R1, rel_err 5.9e-8)
//   X [32768,256] fp32, W [256,256] fp32 (out[m,e] = sum_d X[m,d] W[e,d]), b [256].
// tcgen05 is unavailable (harness targets compute_103 PTX, no 'a' feature), so use
// baseline-ISA tensor cores: mma.sync m16n8k16 bf16 with hi/lo split (3 terms).

#define MDIM 32768
#define NDIM 256
#define KDIM 256

// W pre-split into bf16 hi/lo, [n][k] with 16B-unit XOR swizzle pre-applied.
__device__ __align__(16) uint8_t g_Whi[256 * 512];
__device__ __align__(16) uint8_t g_Wlo[256 * 512];

// ---------------- helpers ----------------
__device__ __forceinline__ void split2(float a, float b, uint32_t& hi, uint32_t& lo) {
    uint32_t ba = __float_as_uint(a), bb = __float_as_uint(b);
    hi = __byte_perm(ba, bb, 0x7632);                 // truncated bf16 pair {b.hi, a.hi}
    float ra = a - __uint_as_float(ba & 0xFFFF0000u); // residual
    float rb = b - __uint_as_float(bb & 0xFFFF0000u);
    __nv_bfloat162 p = __float22bfloat162_rn(make_float2(ra, rb));
    lo = *reinterpret_cast<uint32_t*>(&p);
}
__device__ __forceinline__ void cp16(uint32_t dst, const void* src) {
    asm volatile("cp.async.cg.shared.global [%0], [%1], 16;"
                 :: "r"(dst), "l"(src) : "memory");
}
__device__ __forceinline__ void ldsm4(uint32_t* r, uint32_t addr) {
    asm volatile("ldmatrix.sync.aligned.m8n8.x4.shared.b16 {%0,%1,%2,%3}, [%4];"
                 : "=r"(r[0]), "=r"(r[1]), "=r"(r[2]), "=r"(r[3]) : "r"(addr));
}
__device__ __forceinline__ void mma_bf16(float* d, const uint32_t* a, const uint32_t* b) {
    asm volatile("mma.sync.aligned.m16n8k16.row.col.f32.bf16.bf16.f32 "
                 "{%0,%1,%2,%3}, {%4,%5,%6,%7}, {%8,%9}, {%0,%1,%2,%3};"
                 : "+f"(d[0]), "+f"(d[1]), "+f"(d[2]), "+f"(d[3])
                 : "r"(a[0]), "r"(a[1]), "r"(a[2]), "r"(a[3]), "r"(b[0]), "r"(b[1]));
}
__device__ __forceinline__ void sts64(uint32_t addr, uint32_t v0, uint32_t v1) {
    asm volatile("st.shared.v2.b32 [%0], {%1,%2};" :: "r"(addr), "r"(v0), "r"(v1)
                 : "memory");
}

// ---------------- W prologue: split + swizzle ----------------
// 8192 threads: t -> row n = t>>5, 16B unit k16 = t&31 (8 bf16 along k).
__global__ void w_convert_kernel(const float* __restrict__ W) {
    int t = blockIdx.x * blockDim.x + threadIdx.x;
    int n = t >> 5, k16 = t & 31;
    const float4* src = reinterpret_cast<const float4*>(&W[(size_t)n * KDIM + k16 * 8]);
    float4 v0 = src[0], v1 = src[1];
    uint4 H, L;
    split2(v0.x, v0.y, H.x, L.x);
    split2(v0.z, v0.w, H.y, L.y);
    split2(v1.x, v1.y, H.z, L.z);
    split2(v1.z, v1.w, H.w, L.w);
    uint32_t off = n * 512 + ((k16 ^ (n & 7)) << 4);   // XOR swizzle on 16B units
    *reinterpret_cast<uint4*>(g_Whi + off) = H;
    *reinterpret_cast<uint4*>(g_Wlo + off) = L;
}

// ---------------- main GEMM ----------------
// SMEM (dynamic, 64KB): Xhi[128x64 bf16] @0, Xlo @16K, Whi[128x64] @32K, Wlo @48K
#define SMEM_BYTES 65536

__global__ __launch_bounds__(256, 2)
void fcgat_hmma(const float* __restrict__ X,
                const float* __restrict__ bias,
                float* __restrict__ out)
{
    extern __shared__ char smem[];
    __shared__ float s_bias[128];
    const uint32_t sb  = (uint32_t)__cvta_generic_to_shared(smem);
    const uint32_t xhi = sb, xlo = sb + 16384u, whi = sb + 32768u, wlo = sb + 49152u;

    const int tid  = threadIdx.x;
    const int lane = tid & 31;
    const int wid  = tid >> 5;
    const int bm   = blockIdx.y * 128;
    const int bn   = blockIdx.x * 128;
    const int m0w  = (wid >> 1) * 32;   // warp M offset within CTA tile
    const int n0w  = (wid & 1) * 64;    // warp N offset

    if (tid < 128) s_bias[tid] = bias[bn + tid];

    float acc[2][8][4] = {};

#pragma unroll 1
    for (int c = 0; c < 4; ++c) {
        // ---- W chunk: raw cp.async of pre-swizzled bf16 tiles ----
#pragma unroll
        for (int i = 0; i < 4; ++i) {
            int q = i * 256 + tid;                 // 0..1023 16B units per array
            int n = q >> 3, u = q & 7;
            uint32_t d = (uint32_t)(n * 128 + u * 16);
            size_t   s = (size_t)(bn + n) * 512 + (size_t)c * 128 + (size_t)u * 16;
            cp16(whi + d, g_Whi + s);
            cp16(wlo + d, g_Wlo + s);
        }
        asm volatile("cp.async.commit_group;" ::: "memory");

        // ---- X chunk: fp32 load, hi/lo split, swizzled STS ----
#pragma unroll
        for (int i = 0; i < 8; ++i) {
            int p  = i * 256 + tid;
            int r  = p >> 4;           // row in M-tile
            int kq = p & 15;           // float4 index along k (within chunk of 64)
            float4 v = *reinterpret_cast<const float4*>(
                &X[(size_t)(bm + r) * KDIM + c * 64 + kq * 4]);
            uint32_t h0, l0, h1, l1;
            split2(v.x, v.y, h0, l0);
            split2(v.z, v.w, h1, l1);
            uint32_t off = (uint32_t)(r * 128) +
                           ((((uint32_t)kq >> 1) << 4) ^ (((uint32_t)r & 7) << 4)) +
                           ((uint32_t)kq & 1) * 8;
            sts64(xhi + off, h0, h1);
            sts64(xlo + off, l0, l1);
        }
        asm volatile("cp.async.wait_group 0;" ::: "memory");
        __syncthreads();

        // ---- tensor-core compute: 3 split terms per k-step ----
#pragma unroll
        for (int ks = 0; ks < 4; ++ks) {
            uint32_t a[2][4], b[16];
            // A = X_hi
#pragma unroll
            for (int t = 0; t < 2; ++t) {
                uint32_t r   = m0w + t * 16 + (lane & 15);
                uint32_t col = ((uint32_t)(ks * 32) + (((uint32_t)lane >> 4) << 4)) ^
                               ((r & 7) << 4);
                ldsm4(a[t], xhi + r * 128 + col);
            }
            // B = W_hi ; term 1: Xhi * Whi
#pragma unroll
            for (int jp = 0; jp < 4; ++jp) {
                uint32_t n   = n0w + jp * 16 + (((uint32_t)lane >> 4) << 3) + (lane & 7);
                uint32_t col = ((uint32_t)(ks * 32) + ((((uint32_t)lane >> 3) & 1) << 4)) ^
                               ((n & 7) << 4);
                ldsm4(&b[jp * 4], whi + n * 128 + col);
            }
#pragma unroll
            for (int t = 0; t < 2; ++t)
#pragma unroll
                for (int j = 0; j < 8; ++j)
                    mma_bf16(acc[t][j], a[t], &b[(j >> 1) * 4 + (j & 1) * 2]);
            // term 2: Xhi * Wlo
#pragma unroll
            for (int jp = 0; jp < 4; ++jp) {
                uint32_t n   = n0w + jp * 16 + (((uint32_t)lane >> 4) << 3) + (lane & 7);
                uint32_t col = ((uint32_t)(ks * 32) + ((((uint32_t)lane >> 3) & 1) << 4)) ^
                               ((n & 7) << 4);
                ldsm4(&b[jp * 4], wlo + n * 128 + col);
            }
#pragma unroll
            for (int t = 0; t < 2; ++t)
#pragma unroll
                for (int j = 0; j < 8; ++j)
                    mma_bf16(acc[t][j], a[t], &b[(j >> 1) * 4 + (j & 1) * 2]);
            // term 3: Xlo * Whi
#pragma unroll
            for (int t = 0; t < 2; ++t) {
                uint32_t r   = m0w + t * 16 + (lane & 15);
                uint32_t col = ((uint32_t)(ks * 32) + (((uint32_t)lane >> 4) << 4)) ^
                               ((r & 7) << 4);
                ldsm4(a[t], xlo + r * 128 + col);
            }
#pragma unroll
            for (int jp = 0; jp < 4; ++jp) {
                uint32_t n   = n0w + jp * 16 + (((uint32_t)lane >> 4) << 3) + (lane & 7);
                uint32_t col = ((uint32_t)(ks * 32) + ((((uint32_t)lane >> 3) & 1) << 4)) ^
                               ((n & 7) << 4);
                ldsm4(&b[jp * 4], whi + n * 128 + col);
            }
#pragma unroll
            for (int t = 0; t < 2; ++t)
#pragma unroll
                for (int j = 0; j < 8; ++j)
                    mma_bf16(acc[t][j], a[t], &b[(j >> 1) * 4 + (j & 1) * 2]);
        }
        __syncthreads();
    }

    // ---- epilogue: bias + relu, float2 stores straight from accumulators ----
#pragma unroll
    for (int j = 0; j < 8; ++j) {
        int col = n0w + j * 8 + (lane & 3) * 2;
        float2 bb = *reinterpret_cast<const float2*>(&s_bias[col]);
#pragma unroll
        for (int t = 0; t < 2; ++t) {
            int row = bm + m0w + t * 16 + (lane >> 2);
            float2 v0, v1;
            v0.x = fmaxf(acc[t][j][0] + bb.x, 0.f);
            v0.y = fmaxf(acc[t][j][1] + bb.y, 0.f);
            v1.x = fmaxf(acc[t][j][2] + bb.x, 0.f);
            v1.y = fmaxf(acc[t][j][3] + bb.y, 0.f);
            *reinterpret_cast<float2*>(&out[(size_t)row * NDIM + bn + col]) = v0;
            *reinterpret_cast<float2*>(&out[(size_t)(row + 8) * NDIM + bn + col]) = v1;
        }
    }
}

// ---------------- launch ----------------
extern "C" void kernel_launch(void* const* d_in, const int* in_sizes, int n_in,
                              void* d_out, int out_size)
{
    const float* x  = (const float*)d_in[0];   // [64,512,256]
    const float* Ww = (const float*)d_in[1];   // [256,256]
    const float* Wb = (const float*)d_in[2];   // [256]
    // att_w / att_b dead (softmax rows sum to 1)
    float* out = (float*)d_out;

    cudaFuncSetAttribute(fcgat_hmma, cudaFuncAttributeMaxDynamicSharedMemorySize,
                         SMEM_BYTES);

    w_convert_kernel<<<32, 256>>>(Ww);
    dim3 grid(NDIM / 128, MDIM / 128);         // (2, 256)
    fcgat_hmma<<<grid, 256, SMEM_BYTES>>>(x, Wb, out);
}